// round 3
// baseline (speedup 1.0000x reference)
#include <cuda_runtime.h>

#define SP     4096          // h*w
#define CC     256
#define NH     4
#define DH     64
#define NG     32
#define CPG    8             // channels per group
#define EPSV   1e-6f

// ---------------- scratch (static device globals; no allocs allowed) -------
__device__ float g_q [2 * CC * SP];   // [b][c][s]
__device__ float g_k [2 * CC * SP];   // [b][c][s]
__device__ float g_v [2 * CC * SP];   // [b][c][s]
__device__ float g_ao[2 * SP * CC];   // [b][s][c]  (attention output)
__device__ float g_mean[2 * 2 * NG];  // [tensor(x=0,y=1)][b][g]
__device__ float g_rstd[2 * 2 * NG];

// ---------------- GroupNorm statistics ------------------------------------
// grid = 128 blocks: idx = tensor*64 + b*32 + g. Each group is a CONTIGUOUS
// 8*4096 = 32768-float range of the [b][c][s] tensor.
__global__ void __launch_bounds__(256) gn_stats_kernel(const float* __restrict__ x,
                                                       const float* __restrict__ y)
{
    int idx = blockIdx.x;
    int t = idx >> 6;
    int b = (idx >> 5) & 1;
    int g = idx & 31;
    const float* p = (t ? y : x) + ((size_t)b * CC + g * CPG) * SP;
    const int N = CPG * SP;

    float s0 = 0.f, s1 = 0.f;
    for (int i = threadIdx.x; i < N; i += 256) {
        float v = p[i];
        s0 += v;
        s1 += v * v;
    }
    #pragma unroll
    for (int o = 16; o; o >>= 1) {
        s0 += __shfl_xor_sync(0xffffffffu, s0, o);
        s1 += __shfl_xor_sync(0xffffffffu, s1, o);
    }
    __shared__ float r0[8], r1[8];
    int lane = threadIdx.x & 31, w = threadIdx.x >> 5;
    if (lane == 0) { r0[w] = s0; r1[w] = s1; }
    __syncthreads();
    if (w == 0) {
        s0 = (lane < 8) ? r0[lane] : 0.f;
        s1 = (lane < 8) ? r1[lane] : 0.f;
        #pragma unroll
        for (int o = 4; o; o >>= 1) {
            s0 += __shfl_xor_sync(0xffffffffu, s0, o);
            s1 += __shfl_xor_sync(0xffffffffu, s1, o);
        }
        if (lane == 0) {
            float mean = s0 / (float)N;
            float var  = s1 / (float)N - mean * mean;
            g_mean[idx] = mean;
            g_rstd[idx] = rsqrtf(var + EPSV);
        }
    }
}

// ---------------- projection GEMM: out[b][co][s] = W @ GN(in) + bias -------
// grid (64, 4, 2) = (s-tile, co-tile, b); 256 threads; 4x4 micro-tile.
__global__ void __launch_bounds__(256) proj_kernel(
    const float* __restrict__ in,      // [b][ci][s]
    const float* __restrict__ w,       // [co][ci]
    const float* __restrict__ bias,    // [co]
    const float* __restrict__ gamma,   // [ci]
    const float* __restrict__ beta,    // [ci]
    const float* __restrict__ meanp,   // [b][g]
    const float* __restrict__ rstdp,   // [b][g]
    float* __restrict__ out,           // [b][co][s]
    float scale)
{
    __shared__ float Ws [64][72];      // [ci][co]
    __shared__ float Ins[64][72];      // [ci][s]

    int b   = blockIdx.z;
    int co0 = blockIdx.y * 64;
    int s0  = blockIdx.x * 64;
    int tid = threadIdx.x;
    int ty = tid >> 4, tx = tid & 15;
    int lrow = tid >> 2;            // 0..63
    int lseg = (tid & 3) * 16;      // 0,16,32,48

    float acc[4][4] = {};

    for (int ci0 = 0; ci0 < CC; ci0 += 64) {
        __syncthreads();
        // W tile, transposed into smem
        {
            const float* wp = w + (size_t)(co0 + lrow) * CC + ci0 + lseg;
            #pragma unroll
            for (int u = 0; u < 4; u++) {
                float4 t4 = *(const float4*)(wp + 4 * u);
                int ci = lseg + 4 * u;
                Ws[ci + 0][lrow] = t4.x;
                Ws[ci + 1][lrow] = t4.y;
                Ws[ci + 2][lrow] = t4.z;
                Ws[ci + 3][lrow] = t4.w;
            }
        }
        // input tile, normalized on load
        {
            int ci = ci0 + lrow;
            int gidx = ci >> 3;
            float mu = meanp[b * NG + gidx];
            float rs = rstdp[b * NG + gidx];
            float a = rs * gamma[ci];
            float c = beta[ci] - mu * a;
            const float* ip = in + ((size_t)b * CC + ci) * SP + s0 + lseg;
            #pragma unroll
            for (int u = 0; u < 4; u++) {
                float4 t4 = *(const float4*)(ip + 4 * u);
                t4.x = t4.x * a + c; t4.y = t4.y * a + c;
                t4.z = t4.z * a + c; t4.w = t4.w * a + c;
                *(float4*)&Ins[lrow][lseg + 4 * u] = t4;
            }
        }
        __syncthreads();
        #pragma unroll 16
        for (int ci = 0; ci < 64; ci++) {
            float4 a4 = *(float4*)&Ws [ci][4 * ty];
            float4 b4 = *(float4*)&Ins[ci][4 * tx];
            float av[4] = {a4.x, a4.y, a4.z, a4.w};
            float bv[4] = {b4.x, b4.y, b4.z, b4.w};
            #pragma unroll
            for (int i = 0; i < 4; i++)
                #pragma unroll
                for (int j = 0; j < 4; j++)
                    acc[i][j] += av[i] * bv[j];
        }
    }
    #pragma unroll
    for (int i = 0; i < 4; i++) {
        int co = co0 + 4 * ty + i;
        float bv = bias[co];
        float4 r;
        r.x = (acc[i][0] + bv) * scale;
        r.y = (acc[i][1] + bv) * scale;
        r.z = (acc[i][2] + bv) * scale;
        r.w = (acc[i][3] + bv) * scale;
        *(float4*)&out[((size_t)b * CC + co) * SP + s0 + 4 * tx] = r;
    }
}

// ---------------- flash attention -----------------------------------------
// grid (64, 8) = (q-tile, b*4+h); 256 threads; BM=BN=64, d=64.
#define QK_STRIDE 68
#define PS_STRIDE 65
#define ATTN_SMEM ((2 * 64 * QK_STRIDE + 64 * PS_STRIDE) * 4)   // 51456 B

__global__ void __launch_bounds__(256) attn_kernel(
    const float* __restrict__ q, const float* __restrict__ k,
    const float* __restrict__ v, float* __restrict__ ao)
{
    extern __shared__ float sm[];
    float* Qs = sm;                        // [d][r]  stride 68
    float* Ks = sm + 64 * QK_STRIDE;       // K: [d][kk] / V: [kk][d], stride 68
    float* Ps = sm + 2 * 64 * QK_STRIDE;   // [kk][r] stride 65

    int bh = blockIdx.y;
    int b = bh >> 2, h = bh & 3;
    int q0 = blockIdx.x * 64;
    int tid = threadIdx.x;
    int ty = tid >> 4, tx = tid & 15;
    int r0 = 4 * ty, c0 = 4 * tx;
    int lrow = tid >> 2;            // d index for loads
    int lseg = (tid & 3) * 16;

    const float* qb = q + ((size_t)b * CC + h * DH) * SP;
    const float* kb = k + ((size_t)b * CC + h * DH) * SP;
    const float* vb = v + ((size_t)b * CC + h * DH) * SP;

    // load Q tile: Qs[d][r]
    {
        const float* qp = qb + (size_t)lrow * SP + q0 + lseg;
        #pragma unroll
        for (int u = 0; u < 4; u++)
            *(float4*)&Qs[lrow * QK_STRIDE + lseg + 4 * u] = *(const float4*)(qp + 4 * u);
    }

    float m[4] = {-1e30f, -1e30f, -1e30f, -1e30f};
    float l[4] = {};
    float O[4][4] = {};

    for (int k0 = 0; k0 < SP; k0 += 64) {
        __syncthreads();
        // K tile: Ks[d][kk]
        {
            const float* kp = kb + (size_t)lrow * SP + k0 + lseg;
            #pragma unroll
            for (int u = 0; u < 4; u++)
                *(float4*)&Ks[lrow * QK_STRIDE + lseg + 4 * u] = *(const float4*)(kp + 4 * u);
        }
        __syncthreads();

        // S = Q K^T  (outer-product over d)
        float sacc[4][4] = {};
        #pragma unroll 16
        for (int d = 0; d < 64; d++) {
            float4 qv = *(float4*)&Qs[d * QK_STRIDE + r0];
            float4 kv = *(float4*)&Ks[d * QK_STRIDE + c0];
            float qa[4] = {qv.x, qv.y, qv.z, qv.w};
            float ka[4] = {kv.x, kv.y, kv.z, kv.w};
            #pragma unroll
            for (int i = 0; i < 4; i++)
                #pragma unroll
                for (int j = 0; j < 4; j++)
                    sacc[i][j] += qa[i] * ka[j];
        }

        // online softmax (row reductions across the 16-lane tx group)
        #pragma unroll
        for (int i = 0; i < 4; i++) {
            float mt = fmaxf(fmaxf(sacc[i][0], sacc[i][1]), fmaxf(sacc[i][2], sacc[i][3]));
            #pragma unroll
            for (int o = 8; o; o >>= 1)
                mt = fmaxf(mt, __shfl_xor_sync(0xffffffffu, mt, o));
            float mn = fmaxf(m[i], mt);
            float corr = __expf(m[i] - mn);
            m[i] = mn;
            float ls = 0.f;
            #pragma unroll
            for (int j = 0; j < 4; j++) {
                float p = __expf(sacc[i][j] - mn);
                sacc[i][j] = p;
                ls += p;
            }
            #pragma unroll
            for (int o = 8; o; o >>= 1)
                ls += __shfl_xor_sync(0xffffffffu, ls, o);
            l[i] = l[i] * corr + ls;
            #pragma unroll
            for (int j = 0; j < 4; j++) O[i][j] *= corr;
        }

        __syncthreads();   // everyone done reading Ks(K) and previous Ps

        // write P tile (Ps[kk][r]) and load V tile transposed (Vs[kk][d] in Ks buf)
        #pragma unroll
        for (int j = 0; j < 4; j++) {
            int kk = c0 + j;
            Ps[kk * PS_STRIDE + r0 + 0] = sacc[0][j];
            Ps[kk * PS_STRIDE + r0 + 1] = sacc[1][j];
            Ps[kk * PS_STRIDE + r0 + 2] = sacc[2][j];
            Ps[kk * PS_STRIDE + r0 + 3] = sacc[3][j];
        }
        {
            const float* vp = vb + (size_t)lrow * SP + k0 + lseg;
            #pragma unroll
            for (int u = 0; u < 4; u++) {
                float4 t4 = *(const float4*)(vp + 4 * u);
                int kk = lseg + 4 * u;
                Ks[(kk + 0) * QK_STRIDE + lrow] = t4.x;
                Ks[(kk + 1) * QK_STRIDE + lrow] = t4.y;
                Ks[(kk + 2) * QK_STRIDE + lrow] = t4.z;
                Ks[(kk + 3) * QK_STRIDE + lrow] = t4.w;
            }
        }
        __syncthreads();

        // O += P V
        #pragma unroll 16
        for (int kk = 0; kk < 64; kk++) {
            float4 vv = *(float4*)&Ks[kk * QK_STRIDE + c0];
            float va[4] = {vv.x, vv.y, vv.z, vv.w};
            float p0 = Ps[kk * PS_STRIDE + r0 + 0];
            float p1 = Ps[kk * PS_STRIDE + r0 + 1];
            float p2 = Ps[kk * PS_STRIDE + r0 + 2];
            float p3 = Ps[kk * PS_STRIDE + r0 + 3];
            #pragma unroll
            for (int j = 0; j < 4; j++) {
                O[0][j] += p0 * va[j];
                O[1][j] += p1 * va[j];
                O[2][j] += p2 * va[j];
                O[3][j] += p3 * va[j];
            }
        }
    }

    // epilogue: normalize, write ao[b][s][c] (c = h*64 + c0+j), float4 along c
    float* aob = ao + (size_t)b * SP * CC + h * DH;
    #pragma unroll
    for (int i = 0; i < 4; i++) {
        float inv = 1.f / l[i];
        float4 r;
        r.x = O[i][0] * inv; r.y = O[i][1] * inv;
        r.z = O[i][2] * inv; r.w = O[i][3] * inv;
        *(float4*)&aob[(size_t)(q0 + r0 + i) * CC + c0] = r;
    }
}

// ---------------- output projection + residual -----------------------------
// out[b][co][s] = sum_c wo[co][c]*ao[b][s][c] + bo[co] + x[b][co][s]
__global__ void __launch_bounds__(256) outproj_kernel(
    const float* __restrict__ ao,      // [b][s][c]
    const float* __restrict__ w,       // [co][c]
    const float* __restrict__ bias,
    const float* __restrict__ x,       // [b][co][s]
    float* __restrict__ out)           // [b][co][s]
{
    __shared__ float Ws [64][72];      // [ci][co]
    __shared__ float Ins[64][72];      // [ci][s]

    int b   = blockIdx.z;
    int co0 = blockIdx.y * 64;
    int s0  = blockIdx.x * 64;
    int tid = threadIdx.x;
    int ty = tid >> 4, tx = tid & 15;
    int lrow = tid >> 2;
    int lseg = (tid & 3) * 16;

    float acc[4][4] = {};

    for (int ci0 = 0; ci0 < CC; ci0 += 64) {
        __syncthreads();
        {
            const float* wp = w + (size_t)(co0 + lrow) * CC + ci0 + lseg;
            #pragma unroll
            for (int u = 0; u < 4; u++) {
                float4 t4 = *(const float4*)(wp + 4 * u);
                int ci = lseg + 4 * u;
                Ws[ci + 0][lrow] = t4.x;
                Ws[ci + 1][lrow] = t4.y;
                Ws[ci + 2][lrow] = t4.z;
                Ws[ci + 3][lrow] = t4.w;
            }
        }
        {
            // ao tile: read [s][ci] coalesced, transpose to Ins[ci][s]
            const float* ap = ao + ((size_t)b * SP + s0 + lrow) * CC + ci0 + lseg;
            #pragma unroll
            for (int u = 0; u < 4; u++) {
                float4 t4 = *(const float4*)(ap + 4 * u);
                int ci = lseg + 4 * u;
                Ins[ci + 0][lrow] = t4.x;
                Ins[ci + 1][lrow] = t4.y;
                Ins[ci + 2][lrow] = t4.z;
                Ins[ci + 3][lrow] = t4.w;
            }
        }
        __syncthreads();
        #pragma unroll 16
        for (int ci = 0; ci < 64; ci++) {
            float4 a4 = *(float4*)&Ws [ci][4 * ty];
            float4 b4 = *(float4*)&Ins[ci][4 * tx];
            float av[4] = {a4.x, a4.y, a4.z, a4.w};
            float bv[4] = {b4.x, b4.y, b4.z, b4.w};
            #pragma unroll
            for (int i = 0; i < 4; i++)
                #pragma unroll
                for (int j = 0; j < 4; j++)
                    acc[i][j] += av[i] * bv[j];
        }
    }
    #pragma unroll
    for (int i = 0; i < 4; i++) {
        int co = co0 + 4 * ty + i;
        float bv = bias[co];
        size_t off = ((size_t)b * CC + co) * SP + s0 + 4 * tx;
        float4 xr = *(const float4*)&x[off];
        float4 r;
        r.x = acc[i][0] + bv + xr.x;
        r.y = acc[i][1] + bv + xr.y;
        r.z = acc[i][2] + bv + xr.z;
        r.w = acc[i][3] + bv + xr.w;
        *(float4*)&out[off] = r;
    }
}

// ---------------- launch ----------------------------------------------------
extern "C" void kernel_launch(void* const* d_in, const int* in_sizes, int n_in,
                              void* d_out, int out_size)
{
    const float* x  = (const float*)d_in[0];
    const float* y  = (const float*)d_in[1];
    const float* g1 = (const float*)d_in[2];
    const float* b1 = (const float*)d_in[3];
    const float* g2 = (const float*)d_in[4];
    const float* b2 = (const float*)d_in[5];
    const float* wq = (const float*)d_in[6];
    const float* bq = (const float*)d_in[7];
    const float* wk = (const float*)d_in[8];
    const float* bk = (const float*)d_in[9];
    const float* wv = (const float*)d_in[10];
    const float* bv = (const float*)d_in[11];
    const float* wo = (const float*)d_in[12];
    const float* bo = (const float*)d_in[13];
    float* out = (float*)d_out;

    float *qp, *kp, *vp, *aop, *mp, *rp;
    cudaGetSymbolAddress((void**)&qp,  g_q);
    cudaGetSymbolAddress((void**)&kp,  g_k);
    cudaGetSymbolAddress((void**)&vp,  g_v);
    cudaGetSymbolAddress((void**)&aop, g_ao);
    cudaGetSymbolAddress((void**)&mp,  g_mean);
    cudaGetSymbolAddress((void**)&rp,  g_rstd);

    gn_stats_kernel<<<128, 256>>>(x, y);

    dim3 pg(64, 4, 2);
    // q from GN(y) with (g2,b2), scaled by ATT^-0.5 = 0.125
    proj_kernel<<<pg, 256>>>(y, wq, bq, g2, b2, mp + 64, rp + 64, qp, 0.125f);
    // k, v from GN(x) with (g1,b1)
    proj_kernel<<<pg, 256>>>(x, wk, bk, g1, b1, mp, rp, kp, 1.0f);
    proj_kernel<<<pg, 256>>>(x, wv, bv, g1, b1, mp, rp, vp, 1.0f);

    cudaFuncSetAttribute(attn_kernel, cudaFuncAttributeMaxDynamicSharedMemorySize,
                         ATTN_SMEM);
    attn_kernel<<<dim3(64, 8), 256, ATTN_SMEM>>>(qp, kp, vp, aop);

    outproj_kernel<<<pg, 256>>>(aop, wo, bo, x, out);
}

// round 4
// speedup vs baseline: 1.0044x; 1.0044x over previous
#include <cuda_runtime.h>

#define SP     4096          // h*w
#define CC     256
#define NH     4
#define DH     64
#define NG     32
#define CPG    8             // channels per group
#define EPSV   1e-6f

// ---------------- scratch (static device globals; no allocs allowed) -------
__device__ float g_q [2 * CC * SP];   // [b][c][s]
__device__ float g_k [2 * CC * SP];   // [b][c][s]
__device__ float g_v [2 * CC * SP];   // [b][c][s]
__device__ float g_ao[2 * SP * CC];   // [b][s][c]  (attention output)
__device__ float g_mean[2 * 2 * NG];  // [tensor(x=0,y=1)][b][g]
__device__ float g_rstd[2 * 2 * NG];

// ---------------- GroupNorm statistics ------------------------------------
// grid = 128 blocks: idx = tensor*64 + b*32 + g. Each group is a CONTIGUOUS
// 8*4096 = 32768-float range of the [b][c][s] tensor.
__global__ void __launch_bounds__(256) gn_stats_kernel(const float* __restrict__ x,
                                                       const float* __restrict__ y)
{
    int idx = blockIdx.x;
    int t = idx >> 6;
    int b = (idx >> 5) & 1;
    int g = idx & 31;
    const float* p = (t ? y : x) + ((size_t)b * CC + g * CPG) * SP;
    const int N = CPG * SP;

    float s0 = 0.f, s1 = 0.f;
    for (int i = threadIdx.x; i < N; i += 256) {
        float v = p[i];
        s0 += v;
        s1 += v * v;
    }
    #pragma unroll
    for (int o = 16; o; o >>= 1) {
        s0 += __shfl_xor_sync(0xffffffffu, s0, o);
        s1 += __shfl_xor_sync(0xffffffffu, s1, o);
    }
    __shared__ float r0[8], r1[8];
    int lane = threadIdx.x & 31, w = threadIdx.x >> 5;
    if (lane == 0) { r0[w] = s0; r1[w] = s1; }
    __syncthreads();
    if (w == 0) {
        s0 = (lane < 8) ? r0[lane] : 0.f;
        s1 = (lane < 8) ? r1[lane] : 0.f;
        #pragma unroll
        for (int o = 4; o; o >>= 1) {
            s0 += __shfl_xor_sync(0xffffffffu, s0, o);
            s1 += __shfl_xor_sync(0xffffffffu, s1, o);
        }
        if (lane == 0) {
            float mean = s0 / (float)N;
            float var  = s1 / (float)N - mean * mean;
            g_mean[idx] = mean;
            g_rstd[idx] = rsqrtf(var + EPSV);
        }
    }
}

// ---------------- projection GEMM: out[b][co][s] = W @ GN(in) + bias -------
// grid (64, 4, 2) = (s-tile, co-tile, b); 256 threads; 4x4 micro-tile.
__global__ void __launch_bounds__(256) proj_kernel(
    const float* __restrict__ in,      // [b][ci][s]
    const float* __restrict__ w,       // [co][ci]
    const float* __restrict__ bias,    // [co]
    const float* __restrict__ gamma,   // [ci]
    const float* __restrict__ beta,    // [ci]
    const float* __restrict__ meanp,   // [b][g]
    const float* __restrict__ rstdp,   // [b][g]
    float* __restrict__ out,           // [b][co][s]
    float scale)
{
    __shared__ float Ws [64][72];      // [ci][co]
    __shared__ float Ins[64][72];      // [ci][s]

    int b   = blockIdx.z;
    int co0 = blockIdx.y * 64;
    int s0  = blockIdx.x * 64;
    int tid = threadIdx.x;
    int ty = tid >> 4, tx = tid & 15;
    int lrow = tid >> 2;            // 0..63
    int lseg = (tid & 3) * 16;      // 0,16,32,48

    float acc[4][4] = {};

    for (int ci0 = 0; ci0 < CC; ci0 += 64) {
        __syncthreads();
        // W tile, transposed into smem
        {
            const float* wp = w + (size_t)(co0 + lrow) * CC + ci0 + lseg;
            #pragma unroll
            for (int u = 0; u < 4; u++) {
                float4 t4 = *(const float4*)(wp + 4 * u);
                int ci = lseg + 4 * u;
                Ws[ci + 0][lrow] = t4.x;
                Ws[ci + 1][lrow] = t4.y;
                Ws[ci + 2][lrow] = t4.z;
                Ws[ci + 3][lrow] = t4.w;
            }
        }
        // input tile, normalized on load
        {
            int ci = ci0 + lrow;
            int gidx = ci >> 3;
            float mu = meanp[b * NG + gidx];
            float rs = rstdp[b * NG + gidx];
            float a = rs * gamma[ci];
            float c = beta[ci] - mu * a;
            const float* ip = in + ((size_t)b * CC + ci) * SP + s0 + lseg;
            #pragma unroll
            for (int u = 0; u < 4; u++) {
                float4 t4 = *(const float4*)(ip + 4 * u);
                t4.x = t4.x * a + c; t4.y = t4.y * a + c;
                t4.z = t4.z * a + c; t4.w = t4.w * a + c;
                *(float4*)&Ins[lrow][lseg + 4 * u] = t4;
            }
        }
        __syncthreads();
        #pragma unroll 16
        for (int ci = 0; ci < 64; ci++) {
            float4 a4 = *(float4*)&Ws [ci][4 * ty];
            float4 b4 = *(float4*)&Ins[ci][4 * tx];
            float av[4] = {a4.x, a4.y, a4.z, a4.w};
            float bv[4] = {b4.x, b4.y, b4.z, b4.w};
            #pragma unroll
            for (int i = 0; i < 4; i++)
                #pragma unroll
                for (int j = 0; j < 4; j++)
                    acc[i][j] += av[i] * bv[j];
        }
    }
    #pragma unroll
    for (int i = 0; i < 4; i++) {
        int co = co0 + 4 * ty + i;
        float bv = bias[co];
        float4 r;
        r.x = (acc[i][0] + bv) * scale;
        r.y = (acc[i][1] + bv) * scale;
        r.z = (acc[i][2] + bv) * scale;
        r.w = (acc[i][3] + bv) * scale;
        *(float4*)&out[((size_t)b * CC + co) * SP + s0 + 4 * tx] = r;
    }
}

// ---------------- flash attention -----------------------------------------
// grid (64, 8) = (q-tile, b*4+h); 256 threads; BM=BN=64, d=64.
#define QK_STRIDE 68
#define PS_STRIDE 65
#define ATTN_SMEM ((2 * 64 * QK_STRIDE + 64 * PS_STRIDE) * 4)   // 51456 B

__global__ void __launch_bounds__(256) attn_kernel(
    const float* __restrict__ q, const float* __restrict__ k,
    const float* __restrict__ v, float* __restrict__ ao)
{
    extern __shared__ float sm[];
    float* Qs = sm;                        // [d][r]  stride 68
    float* Ks = sm + 64 * QK_STRIDE;       // K: [d][kk] / V: [kk][d], stride 68
    float* Ps = sm + 2 * 64 * QK_STRIDE;   // [kk][r] stride 65

    int bh = blockIdx.y;
    int b = bh >> 2, h = bh & 3;
    int q0 = blockIdx.x * 64;
    int tid = threadIdx.x;
    int ty = tid >> 4, tx = tid & 15;
    int r0 = 4 * ty, c0 = 4 * tx;
    int lrow = tid >> 2;            // d index for loads
    int lseg = (tid & 3) * 16;

    const float* qb = q + ((size_t)b * CC + h * DH) * SP;
    const float* kb = k + ((size_t)b * CC + h * DH) * SP;
    const float* vb = v + ((size_t)b * CC + h * DH) * SP;

    // load Q tile: Qs[d][r]
    {
        const float* qp = qb + (size_t)lrow * SP + q0 + lseg;
        #pragma unroll
        for (int u = 0; u < 4; u++)
            *(float4*)&Qs[lrow * QK_STRIDE + lseg + 4 * u] = *(const float4*)(qp + 4 * u);
    }

    float m[4] = {-1e30f, -1e30f, -1e30f, -1e30f};
    float l[4] = {};
    float O[4][4] = {};

    for (int k0 = 0; k0 < SP; k0 += 64) {
        __syncthreads();
        // K tile: Ks[d][kk]
        {
            const float* kp = kb + (size_t)lrow * SP + k0 + lseg;
            #pragma unroll
            for (int u = 0; u < 4; u++)
                *(float4*)&Ks[lrow * QK_STRIDE + lseg + 4 * u] = *(const float4*)(kp + 4 * u);
        }
        __syncthreads();

        // S = Q K^T  (outer-product over d)
        float sacc[4][4] = {};
        #pragma unroll 16
        for (int d = 0; d < 64; d++) {
            float4 qv = *(float4*)&Qs[d * QK_STRIDE + r0];
            float4 kv = *(float4*)&Ks[d * QK_STRIDE + c0];
            float qa[4] = {qv.x, qv.y, qv.z, qv.w};
            float ka[4] = {kv.x, kv.y, kv.z, kv.w};
            #pragma unroll
            for (int i = 0; i < 4; i++)
                #pragma unroll
                for (int j = 0; j < 4; j++)
                    sacc[i][j] += qa[i] * ka[j];
        }

        // online softmax (row reductions across the 16-lane tx group)
        #pragma unroll
        for (int i = 0; i < 4; i++) {
            float mt = fmaxf(fmaxf(sacc[i][0], sacc[i][1]), fmaxf(sacc[i][2], sacc[i][3]));
            #pragma unroll
            for (int o = 8; o; o >>= 1)
                mt = fmaxf(mt, __shfl_xor_sync(0xffffffffu, mt, o));
            float mn = fmaxf(m[i], mt);
            float corr = __expf(m[i] - mn);
            m[i] = mn;
            float ls = 0.f;
            #pragma unroll
            for (int j = 0; j < 4; j++) {
                float p = __expf(sacc[i][j] - mn);
                sacc[i][j] = p;
                ls += p;
            }
            #pragma unroll
            for (int o = 8; o; o >>= 1)
                ls += __shfl_xor_sync(0xffffffffu, ls, o);
            l[i] = l[i] * corr + ls;
            #pragma unroll
            for (int j = 0; j < 4; j++) O[i][j] *= corr;
        }

        __syncthreads();   // everyone done reading Ks(K) and previous Ps

        // write P tile (Ps[kk][r]) and load V tile transposed (Vs[kk][d] in Ks buf)
        #pragma unroll
        for (int j = 0; j < 4; j++) {
            int kk = c0 + j;
            Ps[kk * PS_STRIDE + r0 + 0] = sacc[0][j];
            Ps[kk * PS_STRIDE + r0 + 1] = sacc[1][j];
            Ps[kk * PS_STRIDE + r0 + 2] = sacc[2][j];
            Ps[kk * PS_STRIDE + r0 + 3] = sacc[3][j];
        }
        {
            const float* vp = vb + (size_t)lrow * SP + k0 + lseg;
            #pragma unroll
            for (int u = 0; u < 4; u++) {
                float4 t4 = *(const float4*)(vp + 4 * u);
                int kk = lseg + 4 * u;
                Ks[(kk + 0) * QK_STRIDE + lrow] = t4.x;
                Ks[(kk + 1) * QK_STRIDE + lrow] = t4.y;
                Ks[(kk + 2) * QK_STRIDE + lrow] = t4.z;
                Ks[(kk + 3) * QK_STRIDE + lrow] = t4.w;
            }
        }
        __syncthreads();

        // O += P V
        #pragma unroll 16
        for (int kk = 0; kk < 64; kk++) {
            float4 vv = *(float4*)&Ks[kk * QK_STRIDE + c0];
            float va[4] = {vv.x, vv.y, vv.z, vv.w};
            float p0 = Ps[kk * PS_STRIDE + r0 + 0];
            float p1 = Ps[kk * PS_STRIDE + r0 + 1];
            float p2 = Ps[kk * PS_STRIDE + r0 + 2];
            float p3 = Ps[kk * PS_STRIDE + r0 + 3];
            #pragma unroll
            for (int j = 0; j < 4; j++) {
                O[0][j] += p0 * va[j];
                O[1][j] += p1 * va[j];
                O[2][j] += p2 * va[j];
                O[3][j] += p3 * va[j];
            }
        }
    }

    // epilogue: normalize, write ao[b][s][c] (c = h*64 + c0+j), float4 along c
    float* aob = ao + (size_t)b * SP * CC + h * DH;
    #pragma unroll
    for (int i = 0; i < 4; i++) {
        float inv = 1.f / l[i];
        float4 r;
        r.x = O[i][0] * inv; r.y = O[i][1] * inv;
        r.z = O[i][2] * inv; r.w = O[i][3] * inv;
        *(float4*)&aob[(size_t)(q0 + r0 + i) * CC + c0] = r;
    }
}

// ---------------- output projection + residual -----------------------------
// out[b][co][s] = sum_c wo[co][c]*ao[b][s][c] + bo[co] + x[b][co][s]
__global__ void __launch_bounds__(256) outproj_kernel(
    const float* __restrict__ ao,      // [b][s][c]
    const float* __restrict__ w,       // [co][c]
    const float* __restrict__ bias,
    const float* __restrict__ x,       // [b][co][s]
    float* __restrict__ out)           // [b][co][s]
{
    __shared__ float Ws [64][72];      // [ci][co]
    __shared__ float Ins[64][72];      // [ci][s]

    int b   = blockIdx.z;
    int co0 = blockIdx.y * 64;
    int s0  = blockIdx.x * 64;
    int tid = threadIdx.x;
    int ty = tid >> 4, tx = tid & 15;
    int lrow = tid >> 2;
    int lseg = (tid & 3) * 16;

    float acc[4][4] = {};

    for (int ci0 = 0; ci0 < CC; ci0 += 64) {
        __syncthreads();
        {
            const float* wp = w + (size_t)(co0 + lrow) * CC + ci0 + lseg;
            #pragma unroll
            for (int u = 0; u < 4; u++) {
                float4 t4 = *(const float4*)(wp + 4 * u);
                int ci = lseg + 4 * u;
                Ws[ci + 0][lrow] = t4.x;
                Ws[ci + 1][lrow] = t4.y;
                Ws[ci + 2][lrow] = t4.z;
                Ws[ci + 3][lrow] = t4.w;
            }
        }
        {
            // ao tile: read [s][ci] coalesced, transpose to Ins[ci][s]
            const float* ap = ao + ((size_t)b * SP + s0 + lrow) * CC + ci0 + lseg;
            #pragma unroll
            for (int u = 0; u < 4; u++) {
                float4 t4 = *(const float4*)(ap + 4 * u);
                int ci = lseg + 4 * u;
                Ins[ci + 0][lrow] = t4.x;
                Ins[ci + 1][lrow] = t4.y;
                Ins[ci + 2][lrow] = t4.z;
                Ins[ci + 3][lrow] = t4.w;
            }
        }
        __syncthreads();
        #pragma unroll 16
        for (int ci = 0; ci < 64; ci++) {
            float4 a4 = *(float4*)&Ws [ci][4 * ty];
            float4 b4 = *(float4*)&Ins[ci][4 * tx];
            float av[4] = {a4.x, a4.y, a4.z, a4.w};
            float bv[4] = {b4.x, b4.y, b4.z, b4.w};
            #pragma unroll
            for (int i = 0; i < 4; i++)
                #pragma unroll
                for (int j = 0; j < 4; j++)
                    acc[i][j] += av[i] * bv[j];
        }
    }
    #pragma unroll
    for (int i = 0; i < 4; i++) {
        int co = co0 + 4 * ty + i;
        float bv = bias[co];
        size_t off = ((size_t)b * CC + co) * SP + s0 + 4 * tx;
        float4 xr = *(const float4*)&x[off];
        float4 r;
        r.x = acc[i][0] + bv + xr.x;
        r.y = acc[i][1] + bv + xr.y;
        r.z = acc[i][2] + bv + xr.z;
        r.w = acc[i][3] + bv + xr.w;
        *(float4*)&out[off] = r;
    }
}

// ---------------- launch ----------------------------------------------------
extern "C" void kernel_launch(void* const* d_in, const int* in_sizes, int n_in,
                              void* d_out, int out_size)
{
    const float* x  = (const float*)d_in[0];
    const float* y  = (const float*)d_in[1];
    const float* g1 = (const float*)d_in[2];
    const float* b1 = (const float*)d_in[3];
    const float* g2 = (const float*)d_in[4];
    const float* b2 = (const float*)d_in[5];
    const float* wq = (const float*)d_in[6];
    const float* bq = (const float*)d_in[7];
    const float* wk = (const float*)d_in[8];
    const float* bk = (const float*)d_in[9];
    const float* wv = (const float*)d_in[10];
    const float* bv = (const float*)d_in[11];
    const float* wo = (const float*)d_in[12];
    const float* bo = (const float*)d_in[13];
    float* out = (float*)d_out;

    float *qp, *kp, *vp, *aop, *mp, *rp;
    cudaGetSymbolAddress((void**)&qp,  g_q);
    cudaGetSymbolAddress((void**)&kp,  g_k);
    cudaGetSymbolAddress((void**)&vp,  g_v);
    cudaGetSymbolAddress((void**)&aop, g_ao);
    cudaGetSymbolAddress((void**)&mp,  g_mean);
    cudaGetSymbolAddress((void**)&rp,  g_rstd);

    gn_stats_kernel<<<128, 256>>>(x, y);

    dim3 pg(64, 4, 2);
    // q from GN(y) with (g2,b2), scaled by ATT^-0.5 = 0.125
    proj_kernel<<<pg, 256>>>(y, wq, bq, g2, b2, mp + 64, rp + 64, qp, 0.125f);
    // k, v from GN(x) with (g1,b1)
    proj_kernel<<<pg, 256>>>(x, wk, bk, g1, b1, mp, rp, kp, 1.0f);
    proj_kernel<<<pg, 256>>>(x, wv, bv, g1, b1, mp, rp, vp, 1.0f);

    cudaFuncSetAttribute(attn_kernel, cudaFuncAttributeMaxDynamicSharedMemorySize,
                         ATTN_SMEM);
    attn_kernel<<<dim3(64, 8), 256, ATTN_SMEM>>>(qp, kp, vp, aop);

    outproj_kernel<<<pg, 256>>>(aop, wo, bo, x, out);
}